// round 2
// baseline (speedup 1.0000x reference)
#include <cuda_runtime.h>
#include <cuda_bf16.h>

// Problem constants (fixed-shape problem)
#define B_ 8192
#define M_ 256
#define N_ 512
#define NITER_ 16

// Scratch (device globals; no allocation allowed)
__device__ float g_U[(size_t)B_ * N_];   // u buffer / Wy temp
__device__ float g_V[(size_t)B_ * N_];   // V = Wy @ D^T (iteration-invariant)
__device__ float g_Dt[N_ * N_];          // D^T
__device__ float g_St[N_ * N_];          // S^T
__device__ float g_E[N_ * N_];           // E = D @ S

__device__ __forceinline__ float soft_thr_f(float u, float t) {
    return fmaxf(u - t, 0.f) - fmaxf(-u - t, 0.f);
}

// 512x512 transpose
__global__ void transpose512(const float* __restrict__ in, float* __restrict__ out) {
    __shared__ float tile[32][33];
    int x  = blockIdx.x * 32 + threadIdx.x;
    int y0 = blockIdx.y * 32;
    #pragma unroll
    for (int j = threadIdx.y; j < 32; j += 8)
        tile[j][threadIdx.x] = in[(size_t)(y0 + j) * N_ + x];
    __syncthreads();
    int xo  = blockIdx.y * 32 + threadIdx.x;
    int yo0 = blockIdx.x * 32;
    #pragma unroll
    for (int j = threadIdx.y; j < 32; j += 8)
        out[(size_t)(yo0 + j) * N_ + xo] = tile[threadIdx.x][j];
}

// C[M x Ncols] = op(A)[M x K] @ Bm^T, Bm is [Ncols x K] row-major (NT gemm).
// Optional: += Cadd (ADD_C), soft-threshold applied to A elements (SOFT_A).
// Tiles: 128x128x16, 256 threads, 8x8 per thread, register-staged prefetch.
template <bool ADD_C, bool SOFT_A>
__global__ __launch_bounds__(256)
void gemm_nt(const float* __restrict__ A, const float* __restrict__ Bm,
             const float* __restrict__ Cadd, float* __restrict__ C,
             int K, int Ncols, const float* __restrict__ thr) {
    constexpr int BM = 128, BN = 128, BK = 16;
    __shared__ float As[BK][BM];
    __shared__ float Bs[BK][BN];

    const int tid = threadIdx.x;
    const int bx = blockIdx.x, by = blockIdx.y;
    const float* Ab = A + (size_t)by * BM * K;
    const float* Bb = Bm + (size_t)bx * BN * K;

    float theta = 0.f;
    if (SOFT_A) theta = __ldg(thr);

    // Global->reg staging indices: 512 float4 slots per tile, 2 per thread
    const int r0 = tid >> 2;          // 0..63
    const int c0 = (tid & 3) << 2;    // 0,4,8,12

    float4 sA0, sA1, sB0, sB1;

#define LOAD_TILES(kt_)                                                        \
    do {                                                                       \
        const float* Ak = Ab + (kt_) * BK;                                     \
        const float* Bk = Bb + (kt_) * BK;                                     \
        sA0 = *(const float4*)(Ak + (size_t)r0 * K + c0);                      \
        sA1 = *(const float4*)(Ak + (size_t)(r0 + 64) * K + c0);               \
        sB0 = *(const float4*)(Bk + (size_t)r0 * K + c0);                      \
        sB1 = *(const float4*)(Bk + (size_t)(r0 + 64) * K + c0);               \
    } while (0)

#define STORE_TILES()                                                          \
    do {                                                                       \
        float4 a0 = sA0, a1 = sA1;                                             \
        if (SOFT_A) {                                                          \
            a0.x = soft_thr_f(a0.x, theta); a0.y = soft_thr_f(a0.y, theta);    \
            a0.z = soft_thr_f(a0.z, theta); a0.w = soft_thr_f(a0.w, theta);    \
            a1.x = soft_thr_f(a1.x, theta); a1.y = soft_thr_f(a1.y, theta);    \
            a1.z = soft_thr_f(a1.z, theta); a1.w = soft_thr_f(a1.w, theta);    \
        }                                                                      \
        As[c0 + 0][r0] = a0.x; As[c0 + 1][r0] = a0.y;                          \
        As[c0 + 2][r0] = a0.z; As[c0 + 3][r0] = a0.w;                          \
        As[c0 + 0][r0 + 64] = a1.x; As[c0 + 1][r0 + 64] = a1.y;                \
        As[c0 + 2][r0 + 64] = a1.z; As[c0 + 3][r0 + 64] = a1.w;                \
        Bs[c0 + 0][r0] = sB0.x; Bs[c0 + 1][r0] = sB0.y;                        \
        Bs[c0 + 2][r0] = sB0.z; Bs[c0 + 3][r0] = sB0.w;                        \
        Bs[c0 + 0][r0 + 64] = sB1.x; Bs[c0 + 1][r0 + 64] = sB1.y;              \
        Bs[c0 + 2][r0 + 64] = sB1.z; Bs[c0 + 3][r0 + 64] = sB1.w;              \
    } while (0)

    LOAD_TILES(0);
    STORE_TILES();
    __syncthreads();

    const int rowb = (tid >> 4) * 8;  // 0..120
    const int colb = (tid & 15) * 8;  // 0..120

    float acc[8][8] = {};
    const int KT = K / BK;

    for (int kt = 0; kt < KT; kt++) {
        if (kt + 1 < KT) LOAD_TILES(kt + 1);

        #pragma unroll
        for (int k = 0; k < BK; k++) {
            float a[8], b[8];
            *(float4*)(a)     = *(const float4*)&As[k][rowb];
            *(float4*)(a + 4) = *(const float4*)&As[k][rowb + 4];
            *(float4*)(b)     = *(const float4*)&Bs[k][colb];
            *(float4*)(b + 4) = *(const float4*)&Bs[k][colb + 4];
            #pragma unroll
            for (int i = 0; i < 8; i++)
                #pragma unroll
                for (int j = 0; j < 8; j++)
                    acc[i][j] = fmaf(a[i], b[j], acc[i][j]);
        }
        __syncthreads();
        if (kt + 1 < KT) {
            STORE_TILES();
            __syncthreads();
        }
    }

    // Epilogue
    #pragma unroll
    for (int i = 0; i < 8; i++) {
        size_t row = (size_t)by * BM + rowb + i;
        size_t off = row * Ncols + (size_t)bx * BN + colb;
        float4 v0 = make_float4(acc[i][0], acc[i][1], acc[i][2], acc[i][3]);
        float4 v1 = make_float4(acc[i][4], acc[i][5], acc[i][6], acc[i][7]);
        if (ADD_C) {
            float4 u0 = *(const float4*)(Cadd + off);
            float4 u1 = *(const float4*)(Cadd + off + 4);
            v0.x += u0.x; v0.y += u0.y; v0.z += u0.z; v0.w += u0.w;
            v1.x += u1.x; v1.y += u1.y; v1.z += u1.z; v1.w += u1.w;
        }
        *(float4*)(C + off)     = v0;
        *(float4*)(C + off + 4) = v1;
    }
#undef LOAD_TILES
#undef STORE_TILES
}

extern "C" void kernel_launch(void* const* d_in, const int* in_sizes, int n_in,
                              void* d_out, int out_size) {
    const float* y   = (const float*)d_in[0];  // (B, M)
    const float* S   = (const float*)d_in[1];  // (N, N)
    const float* W   = (const float*)d_in[2];  // (N, M)
    const float* D   = (const float*)d_in[3];  // (N, N)
    const float* thr = (const float*)d_in[4];  // (1, 1)
    float* out = (float*)d_out;                // (NITER+1, B, N)

    float *U, *V, *Dt, *St, *E;
    cudaGetSymbolAddress((void**)&U, g_U);
    cudaGetSymbolAddress((void**)&V, g_V);
    cudaGetSymbolAddress((void**)&Dt, g_Dt);
    cudaGetSymbolAddress((void**)&St, g_St);
    cudaGetSymbolAddress((void**)&E, g_E);

    const size_t BN = (size_t)B_ * N_;
    dim3 tb(32, 8), tg(16, 16);
    dim3 gBig(N_ / 128, B_ / 128);   // (4, 64)
    dim3 gSmall(N_ / 128, N_ / 128); // (4, 4)

    // Prologue
    transpose512<<<tg, tb>>>(D, Dt);
    transpose512<<<tg, tb>>>(S, St);
    cudaMemsetAsync(out, 0, BN * sizeof(float));  // d0 = zeros

    // Wy = y @ W^T  -> U   (K = M_ = 256)
    gemm_nt<false, false><<<gBig, 256>>>(y, W, nullptr, U, M_, N_, nullptr);
    // E = D @ S = D @ (S^T)^T
    gemm_nt<false, false><<<gSmall, 256>>>(D, St, nullptr, E, N_, N_, nullptr);
    // V = Wy @ D^T
    gemm_nt<false, false><<<gBig, 256>>>(U, D, nullptr, V, N_, N_, nullptr);

    // Iterations: u = d @ E^T + V ; d' = soft_thr(u) @ D = soft_thr(u) @ Dt^T
    for (int t = 0; t < NITER_; t++) {
        const float* d_t = out + (size_t)t * BN;
        float* d_next    = out + (size_t)(t + 1) * BN;
        gemm_nt<true, false><<<gBig, 256>>>(d_t, E, V, U, N_, N_, nullptr);
        gemm_nt<false, true><<<gBig, 256>>>(U, Dt, nullptr, d_next, N_, N_, thr);
    }
}

// round 4
// speedup vs baseline: 2.9454x; 2.9454x over previous
#include <cuda_runtime.h>
#include <cuda_bf16.h>
#include <cstdint>

#define B_ 8192
#define M_ 256
#define N_ 512
#define NITER_ 16

// ---------------- device scratch (no allocation allowed) --------------------
__device__ __align__(128) __nv_bfloat16 g_yh[(size_t)B_ * M_], g_yl[(size_t)B_ * M_];
__device__ __align__(128) __nv_bfloat16 g_Wh[N_ * M_], g_Wl[N_ * M_];
__device__ __align__(128) __nv_bfloat16 g_Dh[N_ * N_], g_Dl[N_ * N_];
__device__ __align__(128) __nv_bfloat16 g_Sth[N_ * N_], g_Stl[N_ * N_];
__device__ __align__(128) __nv_bfloat16 g_Dth[N_ * N_], g_Dtl[N_ * N_];
__device__ __align__(128) __nv_bfloat16 g_Eh[N_ * N_], g_El[N_ * N_];
__device__ __align__(128) __nv_bfloat16 g_Wyh[(size_t)B_ * N_], g_Wyl[(size_t)B_ * N_];
__device__ __align__(128) __nv_bfloat16 g_dh[(size_t)B_ * N_], g_dl[(size_t)B_ * N_];
__device__ __align__(128) __nv_bfloat16 g_Ph[(size_t)B_ * N_], g_Pl[(size_t)B_ * N_];
__device__ __align__(128) float g_Vf[(size_t)B_ * N_];

// ---------------- PTX helpers (compute_103 baseline ISA only) ---------------
__device__ __forceinline__ uint32_t smem_u32(const void* p) {
    uint32_t a;
    asm("{ .reg .u64 t; cvta.to.shared.u64 t, %1; cvt.u32.u64 %0, t; }"
        : "=r"(a) : "l"(p));
    return a;
}

__device__ __forceinline__ void cp16(uint32_t saddr, const void* gaddr) {
    asm volatile("cp.async.cg.shared.global [%0], [%1], 16;"
                 :: "r"(saddr), "l"(gaddr));
}
__device__ __forceinline__ void cp_commit() {
    asm volatile("cp.async.commit_group;");
}
template <int N>
__device__ __forceinline__ void cp_wait() {
    asm volatile("cp.async.wait_group %0;" :: "n"(N));
}

__device__ __forceinline__ uint4 ldsm_x4(uint32_t addr) {
    uint4 r;
    asm volatile("ldmatrix.sync.aligned.m8n8.x4.shared.b16 {%0,%1,%2,%3}, [%4];"
                 : "=r"(r.x), "=r"(r.y), "=r"(r.z), "=r"(r.w) : "r"(addr));
    return r;
}

__device__ __forceinline__ void mma_bf16(float* c, uint4 a, uint32_t b0, uint32_t b1) {
    asm volatile(
        "mma.sync.aligned.m16n8k16.row.col.f32.bf16.bf16.f32 "
        "{%0,%1,%2,%3}, {%4,%5,%6,%7}, {%8,%9}, {%0,%1,%2,%3};"
        : "+f"(c[0]), "+f"(c[1]), "+f"(c[2]), "+f"(c[3])
        : "r"(a.x), "r"(a.y), "r"(a.z), "r"(a.w), "r"(b0), "r"(b1));
}

__device__ __forceinline__ float soft_thr_f(float u, float t) {
    return fmaxf(u - t, 0.f) - fmaxf(-u - t, 0.f);
}

// ---------------- split / transpose-split prologue kernels ------------------
__global__ void split_mat(const float* __restrict__ in,
                          __nv_bfloat16* __restrict__ hi,
                          __nv_bfloat16* __restrict__ lo, int n) {
    int i = (blockIdx.x * blockDim.x + threadIdx.x) * 4;
    if (i >= n) return;
    float4 v = *(const float4*)(in + i);
    float x[4] = {v.x, v.y, v.z, v.w};
    __nv_bfloat16 h[4], l[4];
    #pragma unroll
    for (int j = 0; j < 4; j++) {
        h[j] = __float2bfloat16(x[j]);
        l[j] = __float2bfloat16(x[j] - __bfloat162float(h[j]));
    }
    *(__nv_bfloat162*)(hi + i)     = __nv_bfloat162(h[0], h[1]);
    *(__nv_bfloat162*)(hi + i + 2) = __nv_bfloat162(h[2], h[3]);
    *(__nv_bfloat162*)(lo + i)     = __nv_bfloat162(l[0], l[1]);
    *(__nv_bfloat162*)(lo + i + 2) = __nv_bfloat162(l[2], l[3]);
}

// out = in^T for 512x512, emitting bf16 hi/lo split
__global__ void transpose_split512(const float* __restrict__ in,
                                   __nv_bfloat16* __restrict__ hi,
                                   __nv_bfloat16* __restrict__ lo) {
    __shared__ float tile[32][33];
    int x = blockIdx.x * 32 + threadIdx.x;
    int y0 = blockIdx.y * 32;
    #pragma unroll
    for (int j = threadIdx.y; j < 32; j += 8)
        tile[j][threadIdx.x] = in[(size_t)(y0 + j) * N_ + x];
    __syncthreads();
    int xo = blockIdx.y * 32 + threadIdx.x;
    int yo0 = blockIdx.x * 32;
    #pragma unroll
    for (int j = threadIdx.y; j < 32; j += 8) {
        float v = tile[threadIdx.x][j];
        __nv_bfloat16 h = __float2bfloat16(v);
        __nv_bfloat16 l = __float2bfloat16(v - __bfloat162float(h));
        size_t o = (size_t)(yo0 + j) * N_ + xo;
        hi[o] = h;
        lo[o] = l;
    }
}

// ---------------- split-bf16 tensor-core GEMM (mma.sync path) ---------------
// C[Mr x Ncols] = A @ Bm^T where A, Bm are given as bf16 hi/lo splits.
// 3-term emulation: ah*bh + al*bh + ah*bl.
// CTA tile 128x128, 8 warps (2x4), warp tile 64x32, K-chunk 64, double buffer.
// Epilogue: optional +V (fp32), optional soft_thr, write fp32 and/or split.
static constexpr int A_BYTES = 128 * 64 * 2;       // 16384 per matrix
static constexpr int OFF_AH = 0;
static constexpr int OFF_AL = OFF_AH + A_BYTES;
static constexpr int OFF_BH = OFF_AL + A_BYTES;
static constexpr int OFF_BL = OFF_BH + A_BYTES;
static constexpr int STG = 4 * A_BYTES;            // 65536 per stage
static constexpr int SMEM_TOTAL = 2 * STG;         // 131072

template <bool ADD_V, bool SOFT, bool WF32, bool WSPLIT>
__global__ __launch_bounds__(256, 1)
void gemm_tc(const __nv_bfloat16* __restrict__ Ah, const __nv_bfloat16* __restrict__ Al,
             const __nv_bfloat16* __restrict__ Bh, const __nv_bfloat16* __restrict__ Bl,
             const float* __restrict__ Vadd, float* __restrict__ Cf,
             __nv_bfloat16* __restrict__ Chi, __nv_bfloat16* __restrict__ Clo,
             int K, int Ncols, const float* __restrict__ thr) {
    extern __shared__ char sm[];
    const uint32_t sbase = smem_u32(sm);

    const int tid = threadIdx.x;
    const int lane = tid & 31;
    const int wid = tid >> 5;
    const int warp_m = wid & 1;    // 0..1
    const int warp_n = wid >> 1;   // 0..3
    const int bx = blockIdx.x, by = blockIdx.y;

    const size_t Kb = (size_t)K * 2;  // row bytes in global bf16 matrices
    const int rowA0 = by * 128;
    const int rowB0 = bx * 128;

    // cp.async staging indices: 1024 16B-units per matrix, 4 per thread
#define ISSUE_CHUNK(kt_, s_)                                                   \
    do {                                                                       \
        _Pragma("unroll")                                                      \
        for (int i_ = 0; i_ < 4; i_++) {                                       \
            int unit = tid + 256 * i_;                                         \
            int row = unit >> 3, u = unit & 7;                                 \
            uint32_t so = (uint32_t)(s_) * STG + row * 128 +                   \
                          (((u ^ (row & 7)) << 4));                            \
            size_t goA = (size_t)(rowA0 + row) * Kb + (kt_) * 128 + u * 16;    \
            size_t goB = (size_t)(rowB0 + row) * Kb + (kt_) * 128 + u * 16;    \
            cp16(sbase + OFF_AH + so, (const char*)Ah + goA);                  \
            cp16(sbase + OFF_AL + so, (const char*)Al + goA);                  \
            cp16(sbase + OFF_BH + so, (const char*)Bh + goB);                  \
            cp16(sbase + OFF_BL + so, (const char*)Bl + goB);                  \
        }                                                                      \
        cp_commit();                                                           \
    } while (0)

    float acc[4][4][4];
    #pragma unroll
    for (int a = 0; a < 4; a++)
        #pragma unroll
        for (int b = 0; b < 4; b++)
            #pragma unroll
            for (int c = 0; c < 4; c++) acc[a][b][c] = 0.f;

    // ldmatrix per-thread addressing constants
    const int rA = lane & 15;               // A row within 16-row tile
    const int khA = lane >> 4;              // A k-half
    const int sxA = rA & 7;
    const int rB = ((lane >> 4) << 3) + (lane & 7);  // B row within 16-row pair
    const int khB = (lane >> 3) & 1;
    const int sxB = rB & 7;

    uint32_t rowOffA[4], rowOffB[2];
    #pragma unroll
    for (int mi = 0; mi < 4; mi++)
        rowOffA[mi] = (warp_m * 64 + mi * 16 + rA) * 128;
    #pragma unroll
    for (int p = 0; p < 2; p++)
        rowOffB[p] = (warp_n * 32 + p * 16 + rB) * 128;

    const int KT = K >> 6;

    ISSUE_CHUNK(0, 0);

    for (int kt = 0; kt < KT; kt++) {
        if (kt + 1 < KT) {
            ISSUE_CHUNK(kt + 1, (kt + 1) & 1);
            cp_wait<1>();
        } else {
            cp_wait<0>();
        }
        __syncthreads();

        const uint32_t st = sbase + (kt & 1) * STG;
        #pragma unroll
        for (int ks = 0; ks < 4; ks++) {
            const uint32_t uA = (uint32_t)(((ks * 2 + khA) ^ sxA) << 4);
            const uint32_t uB = (uint32_t)(((ks * 2 + khB) ^ sxB) << 4);
            uint4 ah[4], al[4];
            #pragma unroll
            for (int mi = 0; mi < 4; mi++) {
                ah[mi] = ldsm_x4(st + OFF_AH + rowOffA[mi] + uA);
                al[mi] = ldsm_x4(st + OFF_AL + rowOffA[mi] + uA);
            }
            uint4 bh0 = ldsm_x4(st + OFF_BH + rowOffB[0] + uB);
            uint4 bh1 = ldsm_x4(st + OFF_BH + rowOffB[1] + uB);
            uint4 bl0 = ldsm_x4(st + OFF_BL + rowOffB[0] + uB);
            uint4 bl1 = ldsm_x4(st + OFF_BL + rowOffB[1] + uB);

            #pragma unroll
            for (int mi = 0; mi < 4; mi++) {
                mma_bf16(acc[mi][0], ah[mi], bh0.x, bh0.y);
                mma_bf16(acc[mi][0], al[mi], bh0.x, bh0.y);
                mma_bf16(acc[mi][0], ah[mi], bl0.x, bl0.y);
                mma_bf16(acc[mi][1], ah[mi], bh0.z, bh0.w);
                mma_bf16(acc[mi][1], al[mi], bh0.z, bh0.w);
                mma_bf16(acc[mi][1], ah[mi], bl0.z, bl0.w);
                mma_bf16(acc[mi][2], ah[mi], bh1.x, bh1.y);
                mma_bf16(acc[mi][2], al[mi], bh1.x, bh1.y);
                mma_bf16(acc[mi][2], ah[mi], bl1.x, bl1.y);
                mma_bf16(acc[mi][3], ah[mi], bh1.z, bh1.w);
                mma_bf16(acc[mi][3], al[mi], bh1.z, bh1.w);
                mma_bf16(acc[mi][3], ah[mi], bl1.z, bl1.w);
            }
        }
        __syncthreads();
    }
#undef ISSUE_CHUNK

    // ---------------- epilogue ----------------
    const float theta = SOFT ? __ldg(thr) : 0.f;
    const int g = lane >> 2, tm = lane & 3;

    #pragma unroll
    for (int mi = 0; mi < 4; mi++) {
        #pragma unroll
        for (int half = 0; half < 2; half++) {
            const int row = by * 128 + warp_m * 64 + mi * 16 + g + half * 8;
            #pragma unroll
            for (int ni = 0; ni < 4; ni++) {
                const int col = bx * 128 + warp_n * 32 + ni * 8 + tm * 2;
                size_t off = (size_t)row * Ncols + col;
                float c0 = acc[mi][ni][half * 2 + 0];
                float c1 = acc[mi][ni][half * 2 + 1];
                if (ADD_V) {
                    float2 v = *(const float2*)(Vadd + off);
                    c0 += v.x;
                    c1 += v.y;
                }
                if (SOFT) {
                    c0 = soft_thr_f(c0, theta);
                    c1 = soft_thr_f(c1, theta);
                }
                if (WF32) *(float2*)(Cf + off) = make_float2(c0, c1);
                if (WSPLIT) {
                    __nv_bfloat16 h0 = __float2bfloat16(c0);
                    __nv_bfloat16 h1 = __float2bfloat16(c1);
                    __nv_bfloat16 l0 = __float2bfloat16(c0 - __bfloat162float(h0));
                    __nv_bfloat16 l1 = __float2bfloat16(c1 - __bfloat162float(h1));
                    *(__nv_bfloat162*)(Chi + off) = __nv_bfloat162(h0, h1);
                    *(__nv_bfloat162*)(Clo + off) = __nv_bfloat162(l0, l1);
                }
            }
        }
    }
}

// ---------------- launch ----------------------------------------------------
extern "C" void kernel_launch(void* const* d_in, const int* in_sizes, int n_in,
                              void* d_out, int out_size) {
    const float* y   = (const float*)d_in[0];  // (B, M)
    const float* S   = (const float*)d_in[1];  // (N, N)
    const float* W   = (const float*)d_in[2];  // (N, M)
    const float* D   = (const float*)d_in[3];  // (N, N)
    const float* thr = (const float*)d_in[4];  // (1, 1)
    float* out = (float*)d_out;                // (NITER+1, B, N)

    __nv_bfloat16 *yh, *yl, *Wh, *Wl, *Dh, *Dl, *Sth, *Stl, *Dth, *Dtl;
    __nv_bfloat16 *Eh, *El, *Wyh, *Wyl, *dh, *dl, *Ph, *Pl;
    float* Vf;
    cudaGetSymbolAddress((void**)&yh, g_yh);   cudaGetSymbolAddress((void**)&yl, g_yl);
    cudaGetSymbolAddress((void**)&Wh, g_Wh);   cudaGetSymbolAddress((void**)&Wl, g_Wl);
    cudaGetSymbolAddress((void**)&Dh, g_Dh);   cudaGetSymbolAddress((void**)&Dl, g_Dl);
    cudaGetSymbolAddress((void**)&Sth, g_Sth); cudaGetSymbolAddress((void**)&Stl, g_Stl);
    cudaGetSymbolAddress((void**)&Dth, g_Dth); cudaGetSymbolAddress((void**)&Dtl, g_Dtl);
    cudaGetSymbolAddress((void**)&Eh, g_Eh);   cudaGetSymbolAddress((void**)&El, g_El);
    cudaGetSymbolAddress((void**)&Wyh, g_Wyh); cudaGetSymbolAddress((void**)&Wyl, g_Wyl);
    cudaGetSymbolAddress((void**)&dh, g_dh);   cudaGetSymbolAddress((void**)&dl, g_dl);
    cudaGetSymbolAddress((void**)&Ph, g_Ph);   cudaGetSymbolAddress((void**)&Pl, g_Pl);
    cudaGetSymbolAddress((void**)&Vf, g_Vf);

    cudaFuncSetAttribute((const void*)gemm_tc<false, false, false, true>,
                         cudaFuncAttributeMaxDynamicSharedMemorySize, SMEM_TOTAL);
    cudaFuncSetAttribute((const void*)gemm_tc<false, false, true, false>,
                         cudaFuncAttributeMaxDynamicSharedMemorySize, SMEM_TOTAL);
    cudaFuncSetAttribute((const void*)gemm_tc<true, true, false, true>,
                         cudaFuncAttributeMaxDynamicSharedMemorySize, SMEM_TOTAL);
    cudaFuncSetAttribute((const void*)gemm_tc<false, false, true, true>,
                         cudaFuncAttributeMaxDynamicSharedMemorySize, SMEM_TOTAL);

    const size_t BN = (size_t)B_ * N_;
    dim3 tb(32, 8), tg(16, 16);
    dim3 gBig(N_ / 128, B_ / 128);   // (4, 64)
    dim3 gSmall(N_ / 128, N_ / 128); // (4, 4)

    // ---- prologue: splits ----
    split_mat<<<(B_ * M_ / 4 + 255) / 256, 256>>>(y, yh, yl, B_ * M_);
    split_mat<<<(N_ * M_ / 4 + 255) / 256, 256>>>(W, Wh, Wl, N_ * M_);
    split_mat<<<(N_ * N_ / 4 + 255) / 256, 256>>>(D, Dh, Dl, N_ * N_);
    transpose_split512<<<tg, tb>>>(S, Sth, Stl);   // St = S^T
    transpose_split512<<<tg, tb>>>(D, Dth, Dtl);   // Dt = D^T

    // Wy = y @ W^T  (K = 256) -> split only
    gemm_tc<false, false, false, true><<<gBig, 256, SMEM_TOTAL>>>(
        yh, yl, Wh, Wl, nullptr, nullptr, Wyh, Wyl, M_, N_, nullptr);
    // E = D @ S = D @ St^T -> split only
    gemm_tc<false, false, false, true><<<gSmall, 256, SMEM_TOTAL>>>(
        Dh, Dl, Sth, Stl, nullptr, nullptr, Eh, El, N_, N_, nullptr);
    // V = Wy @ D^T -> fp32 only
    gemm_tc<false, false, true, false><<<gBig, 256, SMEM_TOTAL>>>(
        Wyh, Wyl, Dh, Dl, nullptr, Vf, nullptr, nullptr, N_, N_, nullptr);

    // d0 = 0
    cudaMemsetAsync(out, 0, BN * sizeof(float));
    cudaMemsetAsync(dh, 0, BN * sizeof(__nv_bfloat16));
    cudaMemsetAsync(dl, 0, BN * sizeof(__nv_bfloat16));

    // Iterations:
    //   P = soft_thr(d @ E^T + V)  -> split(P)
    //   d' = P @ Dt^T              -> out slot (fp32) + split(d')
    for (int t = 0; t < NITER_; t++) {
        float* d_next = out + (size_t)(t + 1) * BN;
        gemm_tc<true, true, false, true><<<gBig, 256, SMEM_TOTAL>>>(
            dh, dl, Eh, El, Vf, nullptr, Ph, Pl, N_, N_, thr);
        gemm_tc<false, false, true, true><<<gBig, 256, SMEM_TOTAL>>>(
            Ph, Pl, Dth, Dtl, nullptr, d_next, dh, dl, N_, N_, nullptr);
    }
}